// round 6
// baseline (speedup 1.0000x reference)
#include <cuda_runtime.h>
#include <stdint.h>

// Output: [B, C, X, Y] fp32
#define BB 4
#define CC 256
#define XX 256
#define YY 256
#define XY (XX * YY)
#define TY 32                 // y-cells per tile
#define NT (YY / TY)          // 8 tiles per (b,x) row

// Inverse index: dense cell (b,x,y) -> (feature row + 1), 0 = empty. 1 MB.
// Zero-initialized at module load; each gather block resets its exclusive
// 256-entry slice to 0, so every launch starts from all-zero state.
__device__ int d_inv[BB * XX * YY];

// ---------------------------------------------------------------------------
// Kernel 1: scatter (row index + 1) into d_inv. Bounds-guarded = mode="drop".
// ---------------------------------------------------------------------------
__global__ void build_inv_kernel(const int* __restrict__ coords, int n) {
    int i = blockIdx.x * blockDim.x + threadIdx.x;
    if (i >= n) return;
    int b = coords[3 * i + 0];
    int x = coords[3 * i + 1];
    int y = coords[3 * i + 2];
    if ((unsigned)b < BB && (unsigned)x < XX && (unsigned)y < YY) {
        d_inv[(b * XX + x) * YY + y] = i + 1;
    }
}

// ---------------------------------------------------------------------------
// Kernel 2: double-buffered pipelined transpose gather.
// One block = one full (b, x) row: 256 y cells = 8 tiles of 32, all 256
// channels. Two 32 KB smem tiles; loads of tile t+1 (cp.async, async) are in
// flight while tile t is transposed and stored -> reads and writes stay
// concurrently outstanding on every SM (no load/store phase alternation).
//
// Tile: float4 tile4[64][TY]; logical (f, y) = channels 4f..4f+3 of cell
// y (within tile), stored at column (y ^ (f & 31)) -> conflict-free in both
// the cp.async fill and the LDS.128 transpose read.
//
// Store: warp w, iter i: f = 8w+i; lane reads tile4[f][lane ^ (f&31)] and
// writes 4 streaming STG.32; lanes contiguous in y -> full 128 B lines.
// Every output element written exactly once (zeros for empty cells).
// ---------------------------------------------------------------------------
__global__ void __launch_bounds__(256)
gather_kernel(const float* __restrict__ feats, float* __restrict__ out) {
    __shared__ int s_inv[YY];
    extern __shared__ float4 tile4[];     // [2][64 * TY]  = 64 KB

    const int L = blockIdx.x * YY;        // base linear cell of this row
    const int b = L >> 16;                // / (XX*YY)
    const int x = (L >> 8) & 255;         // / YY % XX

    const int tid = threadIdx.x;

    // Stage this row's inverse indices; reset exclusive slice to 0.
    {
        int v = d_inv[L + tid];
        s_inv[tid] = v;
        d_inv[L + tid] = 0;
    }
    __syncthreads();

    const int f  = tid & 63;              // float4 group (channels 4f..4f+3)
    const int jb = tid >> 6;              // 0..3
    const int k  = f & 31;                // swizzle key

    // Issue all cp.async loads for one tile (8 independent 16 B copies).
    auto issue_tile = [&](int t) {
        float4* tb = tile4 + (size_t)(t & 1) * (64 * TY);
        #pragma unroll
        for (int wave = 0; wave < 8; wave++) {
            const int j = (wave << 2) + jb;        // y within tile
            const int r = s_inv[t * TY + j];
            const float* src = r ? feats + (size_t)(r - 1) * CC + (f << 2)
                                 : feats;          // valid addr when size==0
            const int size = r ? 16 : 0;           // 0 -> zero-fill
            const uint32_t dst =
                (uint32_t)__cvta_generic_to_shared(&tb[f * TY + (j ^ k)]);
            asm volatile("cp.async.cg.shared.global [%0], [%1], 16, %2;"
                         :: "r"(dst), "l"(src), "r"(size));
        }
        asm volatile("cp.async.commit_group;");
    };

    const int warp = tid >> 5;            // 0..7
    const int lane = tid & 31;            // = y within tile

    issue_tile(0);

    for (int t = 0; t < NT; t++) {
        if (t + 1 < NT) {
            issue_tile(t + 1);
            asm volatile("cp.async.wait_group 1;");   // tile t done
        } else {
            asm volatile("cp.async.wait_group 0;");
        }
        __syncthreads();                  // tile t visible to all threads

        const float4* tb = tile4 + (size_t)(t & 1) * (64 * TY);
        float* op = out + (size_t)b * CC * XY + (size_t)x * YY
                        + t * TY + lane;
        #pragma unroll
        for (int i = 0; i < 8; i++) {
            const int ff = (warp << 3) + i;           // float4 group 0..63
            const float4 v = tb[ff * TY + (lane ^ (ff & 31))];
            float* p = op + (size_t)(ff << 2) * XY;
            __stcs(p,          v.x);
            __stcs(p +     XY, v.y);
            __stcs(p + 2 * XY, v.z);
            __stcs(p + 3 * XY, v.w);
        }
        __syncthreads();                  // buffer free for reuse
    }
}

// ---------------------------------------------------------------------------
// Launcher
// ---------------------------------------------------------------------------
extern "C" void kernel_launch(void* const* d_in, const int* in_sizes, int n_in,
                              void* d_out, int out_size) {
    const float* feats  = (const float*)d_in[0];
    const int*   coords = (const int*)d_in[1];
    float*       out    = (float*)d_out;

    const int n = in_sizes[1] / 3;  // number of sparse points

    const int smem = 2 * 64 * TY * sizeof(float4);   // 64 KB double buffer
    cudaFuncSetAttribute(gather_kernel,
                         cudaFuncAttributeMaxDynamicSharedMemorySize, smem);

    build_inv_kernel<<<(n + 255) / 256, 256>>>(coords, n);
    gather_kernel<<<BB * XX, 256, smem>>>(feats, out);
}

// round 7
// speedup vs baseline: 1.4452x; 1.4452x over previous
#include <cuda_runtime.h>
#include <stdint.h>

// Output: [B, C, X, Y] fp32
#define BB 4
#define CC 256
#define XX 256
#define YY 256
#define XY (XX * YY)

// Inverse index: dense cell (b,x,y) -> (feature row + 1), 0 = empty. 1 MB.
// Zero-initialized at module load; reset_inv_kernel re-zeroes it after every
// gather (stream-ordered), so each launch starts from all-zero state.
__device__ int d_inv[BB * XX * YY];

// ---------------------------------------------------------------------------
// Kernel 1: scatter (row index + 1) into d_inv. Bounds-guarded = mode="drop".
// ---------------------------------------------------------------------------
__global__ void build_inv_kernel(const int* __restrict__ coords, int n) {
    int i = blockIdx.x * blockDim.x + threadIdx.x;
    if (i >= n) return;
    int b = coords[3 * i + 0];
    int x = coords[3 * i + 1];
    int y = coords[3 * i + 2];
    if ((unsigned)b < BB && (unsigned)x < XX && (unsigned)y < YY) {
        d_inv[(b * XX + x) * YY + y] = i + 1;
    }
}

// ---------------------------------------------------------------------------
// Kernel 3: zero the inverse index for the next launch (8 blocks read each
// slice, so the reset can't be fused into the gather without a race).
// ---------------------------------------------------------------------------
__global__ void reset_inv_kernel() {
    int i = blockIdx.x * blockDim.x + threadIdx.x;
    reinterpret_cast<int4*>(d_inv)[i] = make_int4(0, 0, 0, 0);
}

// ---------------------------------------------------------------------------
// Kernel 2: row-locality gather. One block = ALL 256 y cells of one (b, x)
// row x ONE 32-channel group cg. Grid ordered (b, x, cg) with cg fastest:
// the 8 sibling blocks of one (b,x) are co-resident, so their reads of the
// same feats rows (8 x 128 B chunks) cluster in time (1 DRAM row activation
// per 1 KB row), and each block writes 1 KB CONTIGUOUS per channel plane
// (y = 0..255 for its x), with consecutive-x blocks extending the runs.
//
// Tile: float4 tile4[256][8] (32 KB); logical (j = y cell, q = float4 chunk
// of the 32-channel group) stored at column q ^ ((j>>2) & 7).
//  - Load: thread (jb = tid>>3, q = tid&7) fires 8 independent cp.async.cg
//    16 B copies (src-size 0 zero-fills empty cells). Per 128 B phase: one
//    row j, cols q^const = all 8 -> conflict-free, full-line GMEM reads.
//  - Store: warp w, lane l (l7 = l&7, l3 = l>>3) handles channel
//    cg*32 + 4w + l3, y quad 4*l7: reads 4 scalars from rows 32i+4*l7+e at
//    float col (w^l7)*4 + l3 -> bank (w^l7)*4+l3 spans all 32: conflict-free.
//    STG.128: 4 full 128 B lines per warp-op; per channel the 8 iterations
//    write y=0..255 = 1 KB contiguous.
// Every output element written exactly once (zeros for empty cells).
// ---------------------------------------------------------------------------
__global__ void __launch_bounds__(256)
gather_kernel(const float* __restrict__ feats, float* __restrict__ out) {
    __shared__ int    s_inv[YY];
    __shared__ float4 tile4[YY * 8];     // 32 KB

    const int cg = blockIdx.x & 7;       // channel group (32 channels)
    const int bx = blockIdx.x >> 3;      // b*256 + x
    const int b  = bx >> 8;
    const int x  = bx & 255;
    const int L  = bx * YY;              // linear cell base of this (b,x) row

    const int tid = threadIdx.x;

    // Stage this row's inverse indices (shared by 8 sibling blocks; no reset
    // here — reset_inv_kernel does it after the gather).
    s_inv[tid] = d_inv[L + tid];
    __syncthreads();

    // ---- load phase: 8 independent cp.async per thread ----
    const int q  = tid & 7;              // 16 B chunk within 128 B
    const int jb = tid >> 3;             // 0..31: cell within wave
    const int csrc = cg * 32 + (q << 2); // first channel of this chunk

    #pragma unroll
    for (int wave = 0; wave < 8; wave++) {
        const int j = (wave << 5) + jb;  // y cell 0..255
        const int r = s_inv[j];
        const float* src = r ? feats + (size_t)(r - 1) * CC + csrc
                             : feats;    // valid addr even when size==0
        const int size = r ? 16 : 0;     // 0 -> zero-fill 16 B
        const uint32_t dst = (uint32_t)__cvta_generic_to_shared(
            &tile4[(j << 3) + (q ^ ((j >> 2) & 7))]);
        asm volatile("cp.async.cg.shared.global [%0], [%1], 16, %2;"
                     :: "r"(dst), "l"(src), "r"(size));
    }
    asm volatile("cp.async.commit_group;");
    asm volatile("cp.async.wait_group 0;");
    __syncthreads();

    // ---- store phase: 1 KB contiguous per channel, STG.128 full lines ----
    const int w  = tid >> 5;             // warp 0..7 -> channels 4w..4w+3
    const int l  = tid & 31;
    const int l7 = l & 7;
    const int l3 = l >> 3;
    const int colf = ((w ^ l7) << 2) + l3;   // float col within 128 B row

    const float* tf = reinterpret_cast<const float*>(tile4);
    float* op = out + ((size_t)b * CC + cg * 32 + (w << 2) + l3) * XY
                    + (size_t)x * YY + (l7 << 2);

    #pragma unroll
    for (int i = 0; i < 8; i++) {
        const int jbase = (i << 5) + (l7 << 2);  // y = 32i + 4*l7
        float4 v;
        v.x = tf[(jbase + 0) * 32 + colf];
        v.y = tf[(jbase + 1) * 32 + colf];
        v.z = tf[(jbase + 2) * 32 + colf];
        v.w = tf[(jbase + 3) * 32 + colf];
        __stcs(reinterpret_cast<float4*>(op + (i << 5)), v);
    }
}

// ---------------------------------------------------------------------------
// Launcher
// ---------------------------------------------------------------------------
extern "C" void kernel_launch(void* const* d_in, const int* in_sizes, int n_in,
                              void* d_out, int out_size) {
    const float* feats  = (const float*)d_in[0];
    const int*   coords = (const int*)d_in[1];
    float*       out    = (float*)d_out;

    const int n = in_sizes[1] / 3;  // number of sparse points

    build_inv_kernel<<<(n + 255) / 256, 256>>>(coords, n);
    gather_kernel<<<BB * XX * 8, 256>>>(feats, out);
    reset_inv_kernel<<<(BB * XX * YY / 4) / 256, 256>>>();
}